// round 12
// baseline (speedup 1.0000x reference)
#include <cuda_runtime.h>

#define NB 4
#define NA 100000
#define NM 32
#define NC 80
#define TPB 256
#define STREAM_BLOCKS 1250
#define TARGET_BLOCKS 391                 // 391*256 = 100096 >= NA
#define GRID_TOTAL (STREAM_BLOCKS + TARGET_BLOCKS)   // 1641
#define F4_TOTAL (NB * NA * NC / 4)       // 8,000,000
#define F4_PER_STREAM (F4_TOTAL / STREAM_BLOCKS)     // 6400 exactly
#define NEG_W (-0.51986038543f)           /* -0.75 * ln(2) */
#define POS_W (-0.17328679514f)           /* -0.25 * ln(2) */
#define PMAX (1.0f - 1.0e-4f)
#define FULL 0xffffffffu

// [0]=cls_sum, [1]=reg_sum, [2]=num_pos  (zero-init; reset by finalizer block)
__device__ double g_acc[3];
__device__ unsigned int g_count;

__device__ __forceinline__ float warp_sum(float v) {
    #pragma unroll
    for (int o = 16; o > 0; o >>= 1) v += __shfl_down_sync(FULL, v, o);
    return v;
}

__device__ __forceinline__ float huber(float x) {
    float d = fabsf(x);
    return (d < (1.0f / 9.0f)) ? 4.5f * d * d : d - (0.5f / 9.0f);
}

// negative-class focal term (NEG_W applied by caller)
__device__ __forceinline__ float nt(float p) {
    float pu = fminf(p, PMAX);
    return pu * pu * __log2f(1.0f - pu);
}

__device__ __forceinline__ float sum4(float4 v) {
    return (nt(v.x) + nt(v.y)) + (nt(v.z) + nt(v.w));
}

__global__ __launch_bounds__(TPB) void fused_loss_kernel(
    const float*  __restrict__ cls_f,      // (B, A, 80)
    const float4* __restrict__ regression, // (B, A)
    const float4* __restrict__ anchors,    // (A)
    const float*  __restrict__ annotations,// (B, M, 5)
    float* __restrict__ out)
{
    __shared__ float4 sb4[NB * NM];
    __shared__ float  sarea[NB * NM];
    __shared__ float  scls[NB * NM];
    __shared__ float  sred[24];

    const int tid  = threadIdx.x;
    const int lane = tid & 31;
    const int wrp  = tid >> 5;
    const int bid  = blockIdx.x;
    const float4* cls4 = (const float4*)cls_f;

    float cls_c = 0.0f, reg_c = 0.0f, pos_c = 0.0f;

    // interleave 3:1 — every 4th block (mod 4 == 3) among the first 1564 is a target block
    const bool is_target = (bid < 4 * TARGET_BLOCKS) && ((bid & 3) == 3);

    if (!is_target) {
        // ================= STREAM BLOCK: unconditional Σ nt over private span =================
        const int sidx = (bid < 4 * TARGET_BLOCKS) ? (bid - (bid >> 2))
                                                   : (bid - TARGET_BLOCKS);
        const float4* p = cls4 + (size_t)sidx * F4_PER_STREAM + tid;
        float acc0 = 0.0f, acc1 = 0.0f;
        #pragma unroll
        for (int k = 0; k < 6; k++) {
            float4 v0 = __ldcs(p + k * 1024);
            float4 v1 = __ldcs(p + k * 1024 + 256);
            float4 v2 = __ldcs(p + k * 1024 + 512);
            float4 v3 = __ldcs(p + k * 1024 + 768);
            acc0 += sum4(v0) + sum4(v1);
            acc1 += sum4(v2) + sum4(v3);
        }
        acc0 += sum4(__ldcs(p + 6144));      // 25th float4 per thread
        cls_c = NEG_W * (acc0 + acc1);
    } else {
        // ================= TARGET BLOCK: 256 anchors x 4 images =================
        const int a = (bid >> 2) * TPB + tid;
        const bool active = (a < NA);

        float4 an = anchors[active ? a : 0];          // prefetch before barrier

        if (tid < NB * NM) {
            const float* ap = annotations + tid * 5;
            float x1 = ap[0], y1 = ap[1], x2 = ap[2], y2 = ap[3];
            sb4[tid]   = make_float4(x1, y1, x2, y2);
            sarea[tid] = (x2 - x1) * (y2 - y1);
            scls[tid]  = ap[4];
        }
        __syncthreads();

        if (active) {
            const float area_a = (an.z - an.x) * (an.w - an.y);
            const float cx = (an.x + an.z) * 0.5f;
            const float cy = (an.y + an.w) * 0.5f;
            const bool inside = (cx >= 0.0f) && (cx < 800.0f) && (cy >= 0.0f) && (cy < 800.0f);
            const float aw = an.z - an.x, ah = an.w - an.y;

            for (int b = 0; b < NB; b++) {
                const int bm = b * NM;
                float ib = -1.0f, ub = 1.0f;
                int best = 0;
                #pragma unroll
                for (int m = 0; m < NM; m++) {
                    float4 bx = sb4[bm + m];
                    float iw = fminf(an.z, bx.z) - fmaxf(an.x, bx.x);
                    float ih = fminf(an.w, bx.w) - fmaxf(an.y, bx.y);
                    float inter = fmaxf(iw, 0.0f) * fmaxf(ih, 0.0f);
                    float uni = area_a + sarea[bm + m] - inter;
                    if (inter * ub > ib * uni) { ib = inter; ub = uni; best = m; }
                }
                float best_iou = ib / fmaxf(ub, 1e-8f);
                bool pos = best_iou >= 0.5f;
                bool ign = (best_iou > 0.4f) && !pos;

                if (inside && pos) {
                    // positive: reg loss + single-element class correction
                    pos_c += 1.0f;
                    float4 bx = sb4[bm + best];
                    float t0 = ((bx.x - an.x) / aw) * 5.0f;
                    float t1 = ((bx.y - an.y) / ah) * 5.0f;
                    float t2 = ((bx.z - an.z) / aw) * 5.0f;
                    float t3 = ((bx.w - an.w) / ah) * 5.0f;
                    float4 r = regression[(size_t)b * NA + a];
                    reg_c += huber(r.x - t0) + huber(r.y - t1) + huber(r.z - t2) + huber(r.w - t3);

                    int lc = (int)scls[bm + best];
                    float p = cls_f[((size_t)b * NA + a) * NC + lc];
                    float pc = fminf(fmaxf(p, 1.0e-4f), PMAX);
                    float q = 1.0f - pc;
                    cls_c += POS_W * q * q * __log2f(pc) - NEG_W * nt(p);
                } else if (!inside || ign) {
                    // invalid anchor: subtract the 80-element sum the stream blindly added
                    const float4* cp = cls4 + ((size_t)b * NA + a) * 20;
                    float s = 0.0f;
                    #pragma unroll
                    for (int k = 0; k < 5; k++) {
                        float4 v0 = cp[k * 4 + 0];
                        float4 v1 = cp[k * 4 + 1];
                        float4 v2 = cp[k * 4 + 2];
                        float4 v3 = cp[k * 4 + 3];
                        s += (sum4(v0) + sum4(v1)) + (sum4(v2) + sum4(v3));
                    }
                    cls_c -= NEG_W * s;
                }
            }
        }
        __syncthreads();   // protect sred reuse below (uniform: whole block is target)
    }

    // ================= common block reduce + last-block finalize =================
    float wc = warp_sum(cls_c);
    float wr = warp_sum(reg_c);
    float wp = warp_sum(pos_c);
    if (lane == 0) { sred[wrp] = wc; sred[8 + wrp] = wr; sred[16 + wrp] = wp; }
    __syncthreads();
    if (wrp == 0) {
        float vc = (lane < 8) ? sred[lane] : 0.0f;
        float vr = (lane < 8) ? sred[8 + lane] : 0.0f;
        float vp = (lane < 8) ? sred[16 + lane] : 0.0f;
        vc = warp_sum(vc); vr = warp_sum(vr); vp = warp_sum(vp);
        if (lane == 0) {
            atomicAdd(&g_acc[0], (double)vc);
            if (vr != 0.0f) atomicAdd(&g_acc[1], (double)vr);
            if (vp != 0.0f) atomicAdd(&g_acc[2], (double)vp);
            __threadfence();
            unsigned int done = atomicAdd(&g_count, 1u);
            if (done == GRID_TOTAL - 1) {
                double np = g_acc[2];
                if (np < 1.0) np = 1.0;
                out[0] = (float)((g_acc[0] + g_acc[1]) / np);
                g_acc[0] = 0.0; g_acc[1] = 0.0; g_acc[2] = 0.0;
                __threadfence();
                g_count = 0u;
            }
        }
    }
}

extern "C" void kernel_launch(void* const* d_in, const int* in_sizes, int n_in,
                              void* d_out, int out_size) {
    const float* cls = (const float*)d_in[0];  // (B, A, 80)
    const float* reg = (const float*)d_in[1];  // (B, A, 4)
    const float* anc = (const float*)d_in[2];  // (A, 4)
    const float* ann = (const float*)d_in[3];  // (B, M, 5)

    fused_loss_kernel<<<GRID_TOTAL, TPB>>>(
        cls, (const float4*)reg, (const float4*)anc, ann, (float*)d_out);
}

// round 13
// speedup vs baseline: 1.4629x; 1.4629x over previous
#include <cuda_runtime.h>

#define NB 4
#define NA 100000
#define NM 32
#define NC 80
#define TPB 256
#define NBLK_X ((NA + TPB - 1) / TPB)     // 391
#define TOTAL_BLOCKS (NBLK_X * NB)        // 1564
#define NEG_W (-0.51986038543f)           /* -0.75 * ln(2) */
#define POS_W (-0.17328679514f)           /* -0.25 * ln(2) */
#define PMAX (1.0f - 1.0e-4f)
#define FULL 0xffffffffu

// packed f32x2 helpers (sm_100+)
#define PACK2(d, lo, hi)  asm("mov.b64 %0,{%1,%2};" : "=l"(d) : "f"(lo), "f"(hi))
#define UNPACK2(lo, hi, s) asm("mov.b64 {%0,%1},%2;" : "=f"(lo), "=f"(hi) : "l"(s))
#define FMA2(d, a, b, c)  asm("fma.rn.f32x2 %0,%1,%2,%3;" : "=l"(d) : "l"(a), "l"(b), "l"(c))
#define MUL2(d, a, b)     asm("mul.rn.f32x2 %0,%1,%2;"    : "=l"(d) : "l"(a), "l"(b))
#define ADD2(d, a, b)     asm("add.rn.f32x2 %0,%1,%2;"    : "=l"(d) : "l"(a), "l"(b))
#define FMA2ACC(acc, a, b) asm("fma.rn.f32x2 %0,%1,%2,%0;" : "+l"(acc) : "l"(a), "l"(b))

#define NEG1_2 0xBF800000BF800000ull   /* (-1.f,-1.f) */
#define ONE_2  0x3F8000003F800000ull   /* ( 1.f, 1.f) */

// [0]=cls_sum, [1]=reg_sum, [2]=num_pos  (zero-init; reset by finalizer block)
__device__ double g_acc[3];
__device__ unsigned int g_count;

__device__ __forceinline__ float warp_sum(float v) {
    #pragma unroll
    for (int o = 16; o > 0; o >>= 1) v += __shfl_down_sync(FULL, v, o);
    return v;
}

__device__ __forceinline__ float huber(float x) {
    float d = fabsf(x);
    return (d < (1.0f / 9.0f)) ? 4.5f * d * d : d - (0.5f / 9.0f);
}

// scalar negative-class focal term (for the rare correction path; rounding-
// identical to the packed path: fma(p,-1,1)==1-p under rn, mul==mul)
__device__ __forceinline__ float nt(float p) {
    float pu = fminf(p, PMAX);
    return pu * pu * __log2f(1.0f - pu);
}

// packed focal term for one float4: acc2 += (nt2(p01)+nt2(p23)) * (w,w)
__device__ __forceinline__ void nt4_acc(float4 v, float w, unsigned long long& acc2) {
    float p0 = fminf(v.x, PMAX), p1 = fminf(v.y, PMAX);
    float p2 = fminf(v.z, PMAX), p3 = fminf(v.w, PMAX);
    unsigned long long a01, a23, q01, q23, l01, l23, s01, s23, t01, t23, sum2, w2;
    PACK2(a01, p0, p1); PACK2(a23, p2, p3);
    const unsigned long long n1 = NEG1_2, o1 = ONE_2;
    FMA2(q01, a01, n1, o1);      // (1-p0, 1-p1)
    FMA2(q23, a23, n1, o1);
    float q0, q1, q2, q3;
    UNPACK2(q0, q1, q01); UNPACK2(q2, q3, q23);
    float l0 = __log2f(q0), l1 = __log2f(q1), l2 = __log2f(q2), l3 = __log2f(q3);
    PACK2(l01, l0, l1); PACK2(l23, l2, l3);
    MUL2(s01, a01, a01); MUL2(s23, a23, a23);   // p^2
    MUL2(t01, s01, l01); MUL2(t23, s23, l23);   // p^2 * lg2(1-p)
    ADD2(sum2, t01, t23);
    PACK2(w2, w, w);
    FMA2ACC(acc2, sum2, w2);
}

__global__ __launch_bounds__(TPB) void fused_loss_kernel(
    const float*  __restrict__ cls_f,      // (B, A, 80)
    const float4* __restrict__ regression, // (B, A)
    const float4* __restrict__ anchors,    // (A)
    const float*  __restrict__ annotations,// (B, M, 5)
    float* __restrict__ out)
{
    __shared__ float4 sb4[NM];
    __shared__ float  sarea[NM];
    __shared__ float  scls[NM];
    __shared__ float  sred[24];

    const int b    = blockIdx.y;
    const int tid  = threadIdx.x;
    const int lane = tid & 31;
    const int wrp  = tid >> 5;
    const int warp_a0 = blockIdx.x * TPB + wrp * 32;
    const int a    = warp_a0 + lane;
    const bool wactive = (warp_a0 < NA);   // tail warp-aligned (160 = 5*32)

    // shfl-index bases: (lane+32k)/20 = B[k%5] + 8*(k/5)  → only 5 divisions
    unsigned Bidx[5];
    #pragma unroll
    for (int r = 0; r < 5; r++) Bidx[r] = ((unsigned)lane + 32u * r) / 20u;

    // ---- prefetch anchor + first cls batch BEFORE the barrier ----
    float4 an = make_float4(0.f, 0.f, 0.f, 0.f);
    float4 c0, c1, c2, c3;
    const float4* slab = (const float4*)cls_f;
    if (wactive) {
        an   = anchors[a];
        slab = (const float4*)cls_f + ((size_t)b * NA + warp_a0) * 20;
        c0 = __ldcs(slab + lane);
        c1 = __ldcs(slab + lane + 32);
        c2 = __ldcs(slab + lane + 64);
        c3 = __ldcs(slab + lane + 96);
    }

    if (tid < NM) {
        const float* ap = annotations + (b * NM + tid) * 5;
        float x1 = ap[0], y1 = ap[1], x2 = ap[2], y2 = ap[3];
        sb4[tid]   = make_float4(x1, y1, x2, y2);
        sarea[tid] = (x2 - x1) * (y2 - y1);
        scls[tid]  = ap[4];
    }
    __syncthreads();

    float cls_acc = 0.0f, reg_acc = 0.0f, pos_acc = 0.0f;

    if (wactive) {
        // ---- Phase A: per-thread IoU argmax (division-free) ----
        float area_a = (an.z - an.x) * (an.w - an.y);
        float ib = -1.0f, ub = 1.0f;
        int best = 0;
        #pragma unroll
        for (int m = 0; m < NM; m++) {
            float4 bx = sb4[m];
            float iw = fminf(an.z, bx.z) - fmaxf(an.x, bx.x);
            float ih = fminf(an.w, bx.w) - fmaxf(an.y, bx.y);
            float inter = fmaxf(iw, 0.0f) * fmaxf(ih, 0.0f);
            float uni = area_a + sarea[m] - inter;
            if (inter * ub > ib * uni) { ib = inter; ub = uni; best = m; }
        }
        float best_iou = ib / fmaxf(ub, 1e-8f);
        bool pos = best_iou >= 0.5f;
        bool ign = (best_iou > 0.4f) && !pos;
        float cx = (an.x + an.z) * 0.5f;
        float cy = (an.y + an.w) * 0.5f;
        bool inside = (cx >= 0.0f) && (cx < 800.0f) && (cy >= 0.0f) && (cy < 800.0f);
        bool valid = inside && !ign;
        bool is_pos = inside && pos;
        float w = valid ? NEG_W : 0.0f;

        // ---- Phase B: coalesced stream, packed math, division-free shfl idx ----
        unsigned long long acc2 = 0ull;   // packed (0.f, 0.f)
        #pragma unroll
        for (int g = 0; g < 5; g++) {
            if (g > 0) {
                c0 = __ldcs(slab + lane + 32 * (4 * g + 0));
                c1 = __ldcs(slab + lane + 32 * (4 * g + 1));
                c2 = __ldcs(slab + lane + 32 * (4 * g + 2));
                c3 = __ldcs(slab + lane + 32 * (4 * g + 3));
            }
            #pragma unroll
            for (int j = 0; j < 4; j++) {
                const int k = 4 * g + j;
                float wk = __shfl_sync(FULL, w, Bidx[k % 5] + 8 * (k / 5));
                float4 cv = (j == 0) ? c0 : (j == 1) ? c1 : (j == 2) ? c2 : c3;
                nt4_acc(cv, wk, acc2);
            }
        }
        float f0, f1;
        UNPACK2(f0, f1, acc2);
        cls_acc = f0 + f1;

        // ---- positive-anchor extras (rare path) ----
        if (is_pos) {
            pos_acc = 1.0f;
            float4 bx = sb4[best];
            float aw = an.z - an.x, ah = an.w - an.y;
            float t0 = ((bx.x - an.x) / aw) * 5.0f;
            float t1 = ((bx.y - an.y) / ah) * 5.0f;
            float t2 = ((bx.z - an.z) / aw) * 5.0f;
            float t3 = ((bx.w - an.w) / ah) * 5.0f;
            float4 r = regression[(size_t)b * NA + a];
            reg_acc = huber(r.x - t0) + huber(r.y - t1) + huber(r.z - t2) + huber(r.w - t3);

            // correction: + true positive-label term, − the negative term added above
            int lc = (int)scls[best];
            float p = cls_f[((size_t)b * NA + a) * NC + lc];
            float pc = fminf(fmaxf(p, 1.0e-4f), PMAX);
            float q = 1.0f - pc;
            cls_acc += POS_W * q * q * __log2f(pc) - NEG_W * nt(p);
        }
    }

    // ---- Phase C: block reduce (8 warps), 3 double atomics, last-block finalize ----
    float wc = warp_sum(cls_acc);
    float wr = warp_sum(reg_acc);
    float wp = warp_sum(pos_acc);
    if (lane == 0) { sred[wrp] = wc; sred[8 + wrp] = wr; sred[16 + wrp] = wp; }
    __syncthreads();
    if (wrp == 0) {
        float vc = (lane < 8) ? sred[lane] : 0.0f;
        float vr = (lane < 8) ? sred[8 + lane] : 0.0f;
        float vp = (lane < 8) ? sred[16 + lane] : 0.0f;
        vc = warp_sum(vc); vr = warp_sum(vr); vp = warp_sum(vp);
        if (lane == 0) {
            atomicAdd(&g_acc[0], (double)vc);
            if (vr != 0.0f) atomicAdd(&g_acc[1], (double)vr);
            if (vp != 0.0f) atomicAdd(&g_acc[2], (double)vp);
            __threadfence();
            unsigned int done = atomicAdd(&g_count, 1u);
            if (done == TOTAL_BLOCKS - 1) {
                double np = g_acc[2];
                if (np < 1.0) np = 1.0;
                out[0] = (float)((g_acc[0] + g_acc[1]) / np);
                g_acc[0] = 0.0; g_acc[1] = 0.0; g_acc[2] = 0.0;
                __threadfence();
                g_count = 0u;
            }
        }
    }
}

extern "C" void kernel_launch(void* const* d_in, const int* in_sizes, int n_in,
                              void* d_out, int out_size) {
    const float* cls = (const float*)d_in[0];  // (B, A, 80)
    const float* reg = (const float*)d_in[1];  // (B, A, 4)
    const float* anc = (const float*)d_in[2];  // (A, 4)
    const float* ann = (const float*)d_in[3];  // (B, M, 5)

    dim3 grid(NBLK_X, NB);
    fused_loss_kernel<<<grid, TPB>>>(
        cls, (const float4*)reg, (const float4*)anc, ann, (float*)d_out);
}

// round 14
// speedup vs baseline: 1.5410x; 1.0534x over previous
#include <cuda_runtime.h>

#define NB 4
#define NA 100000
#define NM 32
#define NC 80
#define TPB 256
#define NBLK_X ((NA + TPB - 1) / TPB)     // 391
#define TOTAL_BLOCKS (NBLK_X * NB)        // 1564
#define NEG_W (-0.51986038543f)           /* -0.75 * ln(2) */
#define POS_W (-0.17328679514f)           /* -0.25 * ln(2) */
#define PMAX (1.0f - 1.0e-4f)
#define FULL 0xffffffffu

// [0]=cls_sum, [1]=reg_sum, [2]=num_pos  (zero-init; reset by finalizer block)
__device__ double g_acc[3];
__device__ unsigned int g_count;

__device__ __forceinline__ float warp_sum(float v) {
    #pragma unroll
    for (int o = 16; o > 0; o >>= 1) v += __shfl_down_sync(FULL, v, o);
    return v;
}

__device__ __forceinline__ float huber(float x) {
    float d = fabsf(x);
    return (d < (1.0f / 9.0f)) ? 4.5f * d * d : d - (0.5f / 9.0f);
}

// negative-class focal term (weight applied by caller)
__device__ __forceinline__ float nt(float p) {
    float pu = fminf(p, PMAX);
    return pu * pu * __log2f(1.0f - pu);
}

__device__ __forceinline__ float sum4(float4 v) {
    return (nt(v.x) + nt(v.y)) + (nt(v.z) + nt(v.w));
}

__global__ __launch_bounds__(TPB, 8) void fused_loss_kernel(
    const float*  __restrict__ cls_f,      // (B, A, 80)
    const float4* __restrict__ regression, // (B, A)
    const float4* __restrict__ anchors,    // (A)
    const float*  __restrict__ annotations,// (B, M, 5)
    float* __restrict__ out)
{
    __shared__ float4 sb4[NM];    // box coords
    __shared__ float  sarea[NM];  // box areas
    __shared__ float  scls[NM];   // box classes
    __shared__ float  sred[24];

    const int b    = blockIdx.y;
    const int tid  = threadIdx.x;
    const int lane = tid & 31;
    const int wrp  = tid >> 5;
    const int warp_a0 = blockIdx.x * TPB + wrp * 32;
    const int a    = warp_a0 + lane;
    const bool wactive = (warp_a0 < NA);   // tail warp-aligned (160 = 5*32)

    if (tid < NM) {
        const float* ap = annotations + (b * NM + tid) * 5;
        float x1 = ap[0], y1 = ap[1], x2 = ap[2], y2 = ap[3];
        sb4[tid]   = make_float4(x1, y1, x2, y2);
        sarea[tid] = (x2 - x1) * (y2 - y1);
        scls[tid]  = ap[4];
    }
    __syncthreads();

    float cls_acc = 0.0f, reg_acc = 0.0f, pos_acc = 0.0f;

    if (wactive) {
        // ---- Phase A: per-thread IoU argmax (division-free) ----
        // NOTE: `an` is intentionally NOT kept live past this block (reg cap);
        // the rare positive path reloads it.
        float w;
        int best = 0;
        bool is_pos;
        {
            float4 an = anchors[a];
            float area_a = (an.z - an.x) * (an.w - an.y);
            float ib = -1.0f, ub = 1.0f;
            #pragma unroll
            for (int m = 0; m < NM; m++) {
                float4 bx = sb4[m];
                float iw = fminf(an.z, bx.z) - fmaxf(an.x, bx.x);
                float ih = fminf(an.w, bx.w) - fmaxf(an.y, bx.y);
                float inter = fmaxf(iw, 0.0f) * fmaxf(ih, 0.0f);
                float uni = area_a + sarea[m] - inter;
                if (inter * ub > ib * uni) { ib = inter; ub = uni; best = m; }
            }
            float best_iou = ib / fmaxf(ub, 1e-8f);
            bool pos = best_iou >= 0.5f;
            bool ign = (best_iou > 0.4f) && !pos;
            float cx = (an.x + an.z) * 0.5f;
            float cy = (an.y + an.w) * 0.5f;
            bool inside = (cx >= 0.0f) && (cx < 800.0f) && (cy >= 0.0f) && (cy < 800.0f);
            bool valid = inside && !ign;
            is_pos = inside && pos;
            w = valid ? NEG_W : 0.0f;
        }

        // ---- Phase B: warp-cooperative coalesced stream, 2-deep batches ----
        const float4* slab = (const float4*)cls_f + ((size_t)b * NA + warp_a0) * 20 + lane;
        float acc = 0.0f;
        #pragma unroll
        for (int k = 0; k < 20; k += 2) {
            float4 c0 = __ldcs(slab + 32 * k);
            float4 c1 = __ldcs(slab + 32 * (k + 1));
            float w0 = __shfl_sync(FULL, w, ((unsigned)lane + 32u * k) / 20u);
            float w1 = __shfl_sync(FULL, w, ((unsigned)lane + 32u * (k + 1)) / 20u);
            acc = fmaf(sum4(c0), w0, acc);
            acc = fmaf(sum4(c1), w1, acc);
        }
        cls_acc = acc;

        // ---- positive-anchor extras (rare path; reloads anchor) ----
        if (is_pos) {
            pos_acc = 1.0f;
            float4 an = anchors[a];
            float4 bx = sb4[best];
            float aw = an.z - an.x, ah = an.w - an.y;
            float t0 = ((bx.x - an.x) / aw) * 5.0f;
            float t1 = ((bx.y - an.y) / ah) * 5.0f;
            float t2 = ((bx.z - an.z) / aw) * 5.0f;
            float t3 = ((bx.w - an.w) / ah) * 5.0f;
            float4 r = regression[(size_t)b * NA + a];
            reg_acc = huber(r.x - t0) + huber(r.y - t1) + huber(r.z - t2) + huber(r.w - t3);

            // correction: + true positive-label term, − the negative term added above
            int lc = (int)scls[best];
            float p = cls_f[((size_t)b * NA + a) * NC + lc];
            float pc = fminf(fmaxf(p, 1.0e-4f), PMAX);
            float q = 1.0f - pc;
            cls_acc += POS_W * q * q * __log2f(pc) - NEG_W * nt(p);
        }
    }

    // ---- Phase C: block reduce (8 warps), 3 double atomics, last-block finalize ----
    float wc = warp_sum(cls_acc);
    float wr = warp_sum(reg_acc);
    float wp = warp_sum(pos_acc);
    if (lane == 0) { sred[wrp] = wc; sred[8 + wrp] = wr; sred[16 + wrp] = wp; }
    __syncthreads();
    if (wrp == 0) {
        float vc = (lane < 8) ? sred[lane] : 0.0f;
        float vr = (lane < 8) ? sred[8 + lane] : 0.0f;
        float vp = (lane < 8) ? sred[16 + lane] : 0.0f;
        vc = warp_sum(vc); vr = warp_sum(vr); vp = warp_sum(vp);
        if (lane == 0) {
            atomicAdd(&g_acc[0], (double)vc);
            if (vr != 0.0f) atomicAdd(&g_acc[1], (double)vr);
            if (vp != 0.0f) atomicAdd(&g_acc[2], (double)vp);
            __threadfence();
            unsigned int done = atomicAdd(&g_count, 1u);
            if (done == TOTAL_BLOCKS - 1) {
                double np = g_acc[2];
                if (np < 1.0) np = 1.0;
                out[0] = (float)((g_acc[0] + g_acc[1]) / np);
                g_acc[0] = 0.0; g_acc[1] = 0.0; g_acc[2] = 0.0;
                __threadfence();
                g_count = 0u;
            }
        }
    }
}

extern "C" void kernel_launch(void* const* d_in, const int* in_sizes, int n_in,
                              void* d_out, int out_size) {
    const float* cls = (const float*)d_in[0];  // (B, A, 80)
    const float* reg = (const float*)d_in[1];  // (B, A, 4)
    const float* anc = (const float*)d_in[2];  // (A, 4)
    const float* ann = (const float*)d_in[3];  // (B, M, 5)

    dim3 grid(NBLK_X, NB);
    fused_loss_kernel<<<grid, TPB>>>(
        cls, (const float4*)reg, (const float4*)anc, ann, (float*)d_out);
}

// round 15
// speedup vs baseline: 1.6753x; 1.0871x over previous
#include <cuda_runtime.h>

#define NB 4
#define NA 100000
#define NM 32
#define NC 80
#define TPB 256
#define NBLK_X ((NA + TPB - 1) / TPB)     // 391
#define TOTAL_BLOCKS (NBLK_X * NB)        // 1564
#define NSTAGE 8                          // batches staged via cp.async
#define NEG_W (-0.51986038543f)           /* -0.75 * ln(2) */
#define POS_W (-0.17328679514f)           /* -0.25 * ln(2) */
#define PMAX (1.0f - 1.0e-4f)
#define FULL 0xffffffffu

// [0]=cls_sum, [1]=reg_sum, [2]=num_pos  (zero-init; reset by finalizer block)
__device__ double g_acc[3];
__device__ unsigned int g_count;

__device__ __forceinline__ float warp_sum(float v) {
    #pragma unroll
    for (int o = 16; o > 0; o >>= 1) v += __shfl_down_sync(FULL, v, o);
    return v;
}

__device__ __forceinline__ float huber(float x) {
    float d = fabsf(x);
    return (d < (1.0f / 9.0f)) ? 4.5f * d * d : d - (0.5f / 9.0f);
}

// negative-class focal term (weight applied by caller)
__device__ __forceinline__ float nt(float p) {
    float pu = fminf(p, PMAX);
    return pu * pu * __log2f(1.0f - pu);
}

__device__ __forceinline__ float sum4(float4 v) {
    return (nt(v.x) + nt(v.y)) + (nt(v.z) + nt(v.w));
}

__global__ __launch_bounds__(TPB) void fused_loss_kernel(
    const float*  __restrict__ cls_f,      // (B, A, 80)
    const float4* __restrict__ regression, // (B, A)
    const float4* __restrict__ anchors,    // (A)
    const float*  __restrict__ annotations,// (B, M, 5)
    float* __restrict__ out)
{
    __shared__ float4 sstage[NSTAGE * TPB];  // 32KB cp.async staging
    __shared__ float4 sb4[NM];
    __shared__ float  sarea[NM];
    __shared__ float  scls[NM];
    __shared__ float  sred[24];

    const int b    = blockIdx.y;
    const int tid  = threadIdx.x;
    const int lane = tid & 31;
    const int wrp  = tid >> 5;
    const int warp_a0 = blockIdx.x * TPB + wrp * 32;
    const int a    = warp_a0 + lane;
    const bool wactive = (warp_a0 < NA);   // tail warp-aligned (160 = 5*32)

    // ---- issue cp.async for batches 0..7 IMMEDIATELY (no registers held) ----
    const float4* slab = (const float4*)cls_f + ((size_t)b * NA + warp_a0) * 20 + lane;
    if (wactive) {
        #pragma unroll
        for (int k = 0; k < NSTAGE; k++) {
            unsigned sa = (unsigned)__cvta_generic_to_shared(&sstage[k * TPB + tid]);
            asm volatile("cp.async.cg.shared.global [%0], [%1], 16;"
                         :: "r"(sa), "l"(slab + 32 * k) : "memory");
        }
        asm volatile("cp.async.commit_group;" ::: "memory");
    }

    // ---- annotation staging (overlaps with cp.async flight) ----
    if (tid < NM) {
        const float* ap = annotations + (b * NM + tid) * 5;
        float x1 = ap[0], y1 = ap[1], x2 = ap[2], y2 = ap[3];
        sb4[tid]   = make_float4(x1, y1, x2, y2);
        sarea[tid] = (x2 - x1) * (y2 - y1);
        scls[tid]  = ap[4];
    }
    __syncthreads();

    float cls_acc = 0.0f, reg_acc = 0.0f, pos_acc = 0.0f;

    if (wactive) {
        // ---- Phase A: per-thread IoU argmax (division-free) ----
        float4 an = anchors[a];
        float area_a = (an.z - an.x) * (an.w - an.y);
        float ib = -1.0f, ub = 1.0f;
        int best = 0;
        #pragma unroll
        for (int m = 0; m < NM; m++) {
            float4 bx = sb4[m];
            float iw = fminf(an.z, bx.z) - fmaxf(an.x, bx.x);
            float ih = fminf(an.w, bx.w) - fmaxf(an.y, bx.y);
            float inter = fmaxf(iw, 0.0f) * fmaxf(ih, 0.0f);
            float uni = area_a + sarea[m] - inter;
            if (inter * ub > ib * uni) { ib = inter; ub = uni; best = m; }
        }
        float best_iou = ib / fmaxf(ub, 1e-8f);
        bool pos = best_iou >= 0.5f;
        bool ign = (best_iou > 0.4f) && !pos;
        float cx = (an.x + an.z) * 0.5f;
        float cy = (an.y + an.w) * 0.5f;
        bool inside = (cx >= 0.0f) && (cx < 800.0f) && (cy >= 0.0f) && (cy < 800.0f);
        bool valid = inside && !ign;
        bool is_pos = inside && pos;
        float w = valid ? NEG_W : 0.0f;

        // ---- Phase B ----
        float acc = 0.0f;

        // preload global batches 8..11 (land while we consume smem)
        float4 c0 = __ldcs(slab + 32 * 8);
        float4 c1 = __ldcs(slab + 32 * 9);
        float4 c2 = __ldcs(slab + 32 * 10);
        float4 c3 = __ldcs(slab + 32 * 11);

        // consume staged batches 0..7 (producer == consumer thread)
        asm volatile("cp.async.wait_group 0;" ::: "memory");
        #pragma unroll
        for (int k = 0; k < NSTAGE; k++) {
            float4 v = sstage[k * TPB + tid];
            float wk = __shfl_sync(FULL, w, ((unsigned)lane + 32u * k) / 20u);
            acc = fmaf(sum4(v), wk, acc);
        }

        // consume 8..11, then load+consume 12..15 and 16..19 (R7 pattern)
        #pragma unroll
        for (int g = 2; g < 5; g++) {
            const int kb = 4 * g;
            float w0 = __shfl_sync(FULL, w, ((unsigned)lane + 32u * (kb + 0)) / 20u);
            float w1 = __shfl_sync(FULL, w, ((unsigned)lane + 32u * (kb + 1)) / 20u);
            float w2 = __shfl_sync(FULL, w, ((unsigned)lane + 32u * (kb + 2)) / 20u);
            float w3 = __shfl_sync(FULL, w, ((unsigned)lane + 32u * (kb + 3)) / 20u);
            acc = fmaf(sum4(c0), w0, acc);
            acc = fmaf(sum4(c1), w1, acc);
            acc = fmaf(sum4(c2), w2, acc);
            acc = fmaf(sum4(c3), w3, acc);
            if (g < 4) {
                c0 = __ldcs(slab + 32 * (kb + 4));
                c1 = __ldcs(slab + 32 * (kb + 5));
                c2 = __ldcs(slab + 32 * (kb + 6));
                c3 = __ldcs(slab + 32 * (kb + 7));
            }
        }
        cls_acc = acc;

        // ---- positive-anchor extras (rare path) ----
        if (is_pos) {
            pos_acc = 1.0f;
            float4 bx = sb4[best];
            float aw = an.z - an.x, ah = an.w - an.y;
            float t0 = ((bx.x - an.x) / aw) * 5.0f;
            float t1 = ((bx.y - an.y) / ah) * 5.0f;
            float t2 = ((bx.z - an.z) / aw) * 5.0f;
            float t3 = ((bx.w - an.w) / ah) * 5.0f;
            float4 r = regression[(size_t)b * NA + a];
            reg_acc = huber(r.x - t0) + huber(r.y - t1) + huber(r.z - t2) + huber(r.w - t3);

            // correction: + true positive-label term, − the negative term added above
            int lc = (int)scls[best];
            float p = cls_f[((size_t)b * NA + a) * NC + lc];
            float pc = fminf(fmaxf(p, 1.0e-4f), PMAX);
            float q = 1.0f - pc;
            cls_acc += POS_W * q * q * __log2f(pc) - NEG_W * nt(p);
        }
    }

    // ---- Phase C: block reduce (8 warps), 3 double atomics, last-block finalize ----
    float wc = warp_sum(cls_acc);
    float wr = warp_sum(reg_acc);
    float wp = warp_sum(pos_acc);
    if (lane == 0) { sred[wrp] = wc; sred[8 + wrp] = wr; sred[16 + wrp] = wp; }
    __syncthreads();
    if (wrp == 0) {
        float vc = (lane < 8) ? sred[lane] : 0.0f;
        float vr = (lane < 8) ? sred[8 + lane] : 0.0f;
        float vp = (lane < 8) ? sred[16 + lane] : 0.0f;
        vc = warp_sum(vc); vr = warp_sum(vr); vp = warp_sum(vp);
        if (lane == 0) {
            atomicAdd(&g_acc[0], (double)vc);
            if (vr != 0.0f) atomicAdd(&g_acc[1], (double)vr);
            if (vp != 0.0f) atomicAdd(&g_acc[2], (double)vp);
            __threadfence();
            unsigned int done = atomicAdd(&g_count, 1u);
            if (done == TOTAL_BLOCKS - 1) {
                double np = g_acc[2];
                if (np < 1.0) np = 1.0;
                out[0] = (float)((g_acc[0] + g_acc[1]) / np);
                g_acc[0] = 0.0; g_acc[1] = 0.0; g_acc[2] = 0.0;
                __threadfence();
                g_count = 0u;
            }
        }
    }
}

extern "C" void kernel_launch(void* const* d_in, const int* in_sizes, int n_in,
                              void* d_out, int out_size) {
    const float* cls = (const float*)d_in[0];  // (B, A, 80)
    const float* reg = (const float*)d_in[1];  // (B, A, 4)
    const float* anc = (const float*)d_in[2];  // (A, 4)
    const float* ann = (const float*)d_in[3];  // (B, M, 5)

    dim3 grid(NBLK_X, NB);
    fused_loss_kernel<<<grid, TPB>>>(
        cls, (const float4*)reg, (const float4*)anc, ann, (float*)d_out);
}